// round 16
// baseline (speedup 1.0000x reference)
#include <cuda_runtime.h>
#include <cuda_fp16.h>
#include <cstdint>

// Problem constants
#define N_NODES 100000
#define N_EDGES 400000
#define DIM     128
#define KDIM    384       // 3*DIM
#define HID     768       // 6*DIM
#define TILE_M  128
#define N_TILES (N_EDGES / TILE_M)   // 3125
#define KTILES  24
#define N_STEPS 4                    // 768 / 192 n-cols per step
#define N_CHUNKS 32                  // 4 steps x 8 chunks (3 kt each)
#define RING    6

// W1 fp16, m16n8k16 B-fragment order, chunk-grouped:
// [step 4][chunk 8][ntile 24][kt3][lane 32][8B]   (18 KB per chunk)
__device__ __align__(16) __half g_w1frag[HID * KDIM];

static constexpr uint32_t B_STEP_BYTES  = 24 * 24 * 32 * 8;   // 147456
static constexpr uint32_t B_CHUNK_BYTES = B_STEP_BYTES / 8;   // 18432

// ---------------- SMEM layout ----------------
// A (feat frags): [mt8][kt24][lane32][16B] = 98304
static constexpr int SM_A    = 0;
static constexpr int SM_B    = 98304;    // 6 x 18432 ring = 110592
static constexpr int SM_W2   = 208896;   // 768 f32
static constexpr int SM_B1   = 211968;   // 768 f32
static constexpr int SM_PART = 215040;   // 6 x 128 f32 = 3072
static constexpr int SM_MBAR = 218112;   // 6 full + 6 empty mbarriers
static constexpr int SMEM_TOTAL = 218240;

// ---------------- helpers ----------------
__device__ __forceinline__ uint32_t smem_u32(const void* p) {
    uint32_t a;
    asm("{ .reg .u64 t; cvta.to.shared.u64 t, %1; cvt.u32.u64 %0, t; }" : "=r"(a) : "l"(p));
    return a;
}
__device__ __forceinline__ void cp16(uint32_t dst, const void* src) {
    asm volatile("cp.async.cg.shared.global [%0], [%1], 16;" :: "r"(dst), "l"(src) : "memory");
}
__device__ __forceinline__ void cp_arrive_noinc(uint32_t mbar) {
    asm volatile("cp.async.mbarrier.arrive.noinc.shared.b64 [%0];" :: "r"(mbar) : "memory");
}
__device__ __forceinline__ void mbar_init(uint32_t m, uint32_t cnt) {
    asm volatile("mbarrier.init.shared.b64 [%0], %1;" :: "r"(m), "r"(cnt) : "memory");
}
__device__ __forceinline__ void mbar_arrive(uint32_t m) {
    asm volatile("mbarrier.arrive.shared.b64 _, [%0];" :: "r"(m) : "memory");
}
__device__ __forceinline__ void mbar_wait(uint32_t m, uint32_t parity) {
    asm volatile(
        "{\n\t.reg .pred P;\n"
        "LAB%=:\n\t"
        "mbarrier.try_wait.parity.acquire.cta.shared::cta.b64 P, [%0], %1, 0x989680;\n\t"
        "@!P bra LAB%=;\n\t}"
        :: "r"(m), "r"(parity) : "memory");
}
__device__ __forceinline__ void mma16816(float* d, const uint32_t* a, const uint32_t* b) {
    asm volatile(
        "mma.sync.aligned.m16n8k16.row.col.f32.f16.f16.f32 "
        "{%0,%1,%2,%3}, {%4,%5,%6,%7}, {%8,%9}, {%0,%1,%2,%3};"
        : "+f"(d[0]), "+f"(d[1]), "+f"(d[2]), "+f"(d[3])
        : "r"(a[0]), "r"(a[1]), "r"(a[2]), "r"(a[3]), "r"(b[0]), "r"(b[1]));
}

// A-fragment smem byte offset for (row r in 0..127, kpair p in 0..191)
__device__ __forceinline__ uint32_t a_frag_off(int r, int p) {
    int kt   = p >> 3;
    int kp   = p & 7;
    int ln   = ((r & 7) << 2) + (kp & 3);
    int word = ((r >> 3) & 1) + ((kp >> 2) << 1);
    int mt   = r >> 4;
    return (uint32_t)(((mt * KTILES + kt) << 9) + (ln << 4) + (word << 2));
}

// ---------------- prep: W1 fp32 -> fp16 fragment-ordered (chunk-grouped) ----------------
__global__ void prep_w1_kernel(const float* __restrict__ W1) {
    int i = blockIdx.x * blockDim.x + threadIdx.x;
    if (i >= HID * KDIM) return;
    int n = i / KDIM;
    int k = i - n * KDIM;
    int step = n / 192;           // 192 cols per step
    int np   = n - step * 192;
    int nt   = np >> 3;           // 24 ntiles per step
    int g    = np & 7;
    int kt   = k >> 4;            // 0..23
    int ch   = kt / 3;            // chunk within step (0..7)
    int kt3  = kt - ch * 3;
    int kk   = k & 15;
    int w    = kk >> 3;
    int t    = (kk & 7) >> 1;
    int hb   = kk & 1;
    uint32_t off = (uint32_t)step * B_STEP_BYTES + (uint32_t)ch * B_CHUNK_BYTES
                 + (uint32_t)((nt * 3 + kt3) << 8)
                 + (uint32_t)(((g << 2) + t) << 3) + (uint32_t)(w << 2) + (uint32_t)(hb << 1);
    *(__half*)((char*)g_w1frag + off) = __float2half_rn(W1[i]);
}

// ---------------- main fused kernel (warp-specialized, 12 consumers + 1 producer) ----------------
__global__ void __launch_bounds__(416, 1) edge_mlp_ws(
    const float* __restrict__ x,
    const int* __restrict__ ei,     // int32 (JAX x64 disabled)
    const float* __restrict__ b1g,
    const float* __restrict__ w2g,
    const float* __restrict__ b2g,
    float* __restrict__ out)
{
    extern __shared__ char smem[];
    const uint32_t sb = smem_u32(smem);
    const int tid  = threadIdx.x;
    const int lane = tid & 31;
    const int wid  = tid >> 5;
    const bool producer = (wid == 12);
    const int e0 = blockIdx.x * TILE_M;

    const uint32_t FULL  = sb + SM_MBAR;       // 6 x 8 B
    const uint32_t EMPTY = sb + SM_MBAR + 48;  // 6 x 8 B

    if (tid == 0) {
#pragma unroll
        for (int i = 0; i < RING; i++) {
            mbar_init(FULL + i * 8, 32);    // producer cp-arrivals (noinc)
            mbar_init(EMPTY + i * 8, 12);   // one lane-0 arrive per consumer warp
        }
    }
    __syncthreads();   // barriers initialized

    if (producer) {
        // pre-fill chunks 0..RING-1 (ring initially empty)
#pragma unroll
        for (int q = 0; q < RING; q++) {
            const char* src = (const char*)g_w1frag + (uint32_t)q * B_CHUNK_BYTES + (uint32_t)lane * 16u;
            uint32_t dst = sb + SM_B + (uint32_t)q * B_CHUNK_BYTES + (uint32_t)lane * 16u;
#pragma unroll
            for (int j = 0; j < 36; j++)
                cp16(dst + j * 512, src + j * 512);
            cp_arrive_noinc(FULL + q * 8);
        }
    } else if (tid < 256) {
        // stage w2 / b1
        float* w2s = (float*)(smem + SM_W2);
        float* b1s = (float*)(smem + SM_B1);
#pragma unroll
        for (int i = 0; i < 3; i++) { w2s[tid + i * 256] = w2g[tid + i * 256];
                                      b1s[tid + i * 256] = b1g[tid + i * 256]; }

        // build feat tile (kpair bases: mean 0, prod 64, sqdiff 128); 2 threads/row
        const int r  = tid & 127;
        const int qb = (tid >> 7) * 16;
        const int i0 = ei[e0 + r];
        const int i1 = ei[N_EDGES + e0 + r];
        const float4* p0 = (const float4*)x + (size_t)i0 * 32 + qb;
        const float4* p1 = (const float4*)x + (size_t)i1 * 32 + qb;
        char* As = smem + SM_A;
#pragma unroll 4
        for (int q = 0; q < 16; q++) {
            float4 a = p0[q];
            float4 c = p1[q];
            int qg = qb + q;
            __half2 h;
            h = __floats2half2_rn((a.x + c.x) * 0.5f, (a.y + c.y) * 0.5f);
            *(uint32_t*)(As + a_frag_off(r, 2 * qg))          = *(uint32_t*)&h;
            h = __floats2half2_rn((a.z + c.z) * 0.5f, (a.w + c.w) * 0.5f);
            *(uint32_t*)(As + a_frag_off(r, 2 * qg + 1))      = *(uint32_t*)&h;
            h = __floats2half2_rn(a.x * c.x, a.y * c.y);
            *(uint32_t*)(As + a_frag_off(r, 64 + 2 * qg))     = *(uint32_t*)&h;
            h = __floats2half2_rn(a.z * c.z, a.w * c.w);
            *(uint32_t*)(As + a_frag_off(r, 64 + 2 * qg + 1)) = *(uint32_t*)&h;
            float d0 = a.x - c.x, d1 = a.y - c.y, d2 = a.z - c.z, d3 = a.w - c.w;
            h = __floats2half2_rn(d0 * d0, d1 * d1);
            *(uint32_t*)(As + a_frag_off(r, 128 + 2 * qg))     = *(uint32_t*)&h;
            h = __floats2half2_rn(d2 * d2, d3 * d3);
            *(uint32_t*)(As + a_frag_off(r, 128 + 2 * qg + 1)) = *(uint32_t*)&h;
        }
    }
    __syncthreads();   // A + w2/b1 visible

    if (producer) {
        // steady-state: chunk q into ring slot q%RING after consumers drain q-RING
#pragma unroll 1
        for (int q = RING; q < N_CHUNKS; q++) {
            const int slot = q % RING;
            const uint32_t ph = (uint32_t)((q / RING) - 1) & 1u;
            if (lane == 0) mbar_wait(EMPTY + slot * 8, ph);
            __syncwarp();
            const char* src = (const char*)g_w1frag + (uint32_t)q * B_CHUNK_BYTES + (uint32_t)lane * 16u;
            uint32_t dst = sb + SM_B + (uint32_t)slot * B_CHUNK_BYTES + (uint32_t)lane * 16u;
#pragma unroll
            for (int j = 0; j < 36; j++)
                cp16(dst + j * 512, src + j * 512);
            cp_arrive_noinc(FULL + slot * 8);
        }
    } else {
        const int mg = wid & 1;      // 2 m-groups (64 rows = 4 mtiles each)
        const int ng = wid >> 1;     // 6 n-groups (32 cols per step each)
        const int t4 = lane & 3;
        const int g  = lane >> 2;
        float* w2s = (float*)(smem + SM_W2);
        float* b1s = (float*)(smem + SM_B1);

        float accv[8];
#pragma unroll
        for (int i = 0; i < 8; i++) accv[i] = 0.f;

        const uint32_t a_base = (uint32_t)SM_A + (uint32_t)(mg * 4 * KTILES) * 512u + (uint32_t)lane * 16u;
        const uint32_t b_rel  = (uint32_t)ng * 3072u + (uint32_t)lane * 8u;   // ntile = ng*4

        float C[16][4];

#pragma unroll 1
        for (int q = 0; q < N_CHUNKS; q++) {
            const int slot = q % RING;
            const int cs   = q & 7;            // chunk within step
            // lane-0 poll, warp-wide hand-off via bar.warp.sync memory ordering
            if (lane == 0) mbar_wait(FULL + slot * 8, (uint32_t)(q / RING) & 1u);
            __syncwarp();

            if (cs == 0) {
#pragma unroll
                for (int f = 0; f < 16; f++)
#pragma unroll
                    for (int v = 0; v < 4; v++) C[f][v] = 0.f;
            }

            const uint32_t bbuf = (uint32_t)SM_B + (uint32_t)slot * B_CHUNK_BYTES + b_rel;
            const int ktb = cs * 3;            // kt base within K for A
#pragma unroll
            for (int kt = 0; kt < 3; kt++) {
                uint4 A0 = *(const uint4*)(smem + a_base + (uint32_t)(0 * KTILES + ktb + kt) * 512u);
                uint4 A1 = *(const uint4*)(smem + a_base + (uint32_t)(1 * KTILES + ktb + kt) * 512u);
                uint4 A2 = *(const uint4*)(smem + a_base + (uint32_t)(2 * KTILES + ktb + kt) * 512u);
                uint4 A3 = *(const uint4*)(smem + a_base + (uint32_t)(3 * KTILES + ktb + kt) * 512u);
                uint2 B0 = *(const uint2*)(smem + bbuf + (uint32_t)(0 * 3 + kt) * 256u);
                uint2 B1 = *(const uint2*)(smem + bbuf + (uint32_t)(1 * 3 + kt) * 256u);
                uint2 B2 = *(const uint2*)(smem + bbuf + (uint32_t)(2 * 3 + kt) * 256u);
                uint2 B3 = *(const uint2*)(smem + bbuf + (uint32_t)(3 * 3 + kt) * 256u);
                mma16816(C[0],  (const uint32_t*)&A0, (const uint32_t*)&B0);
                mma16816(C[1],  (const uint32_t*)&A0, (const uint32_t*)&B1);
                mma16816(C[2],  (const uint32_t*)&A0, (const uint32_t*)&B2);
                mma16816(C[3],  (const uint32_t*)&A0, (const uint32_t*)&B3);
                mma16816(C[4],  (const uint32_t*)&A1, (const uint32_t*)&B0);
                mma16816(C[5],  (const uint32_t*)&A1, (const uint32_t*)&B1);
                mma16816(C[6],  (const uint32_t*)&A1, (const uint32_t*)&B2);
                mma16816(C[7],  (const uint32_t*)&A1, (const uint32_t*)&B3);
                mma16816(C[8],  (const uint32_t*)&A2, (const uint32_t*)&B0);
                mma16816(C[9],  (const uint32_t*)&A2, (const uint32_t*)&B1);
                mma16816(C[10], (const uint32_t*)&A2, (const uint32_t*)&B2);
                mma16816(C[11], (const uint32_t*)&A2, (const uint32_t*)&B3);
                mma16816(C[12], (const uint32_t*)&A3, (const uint32_t*)&B0);
                mma16816(C[13], (const uint32_t*)&A3, (const uint32_t*)&B1);
                mma16816(C[14], (const uint32_t*)&A3, (const uint32_t*)&B2);
                mma16816(C[15], (const uint32_t*)&A3, (const uint32_t*)&B3);
            }
            // single release-arrive per warp; syncwarp orders all lanes' LDS reads before it
            __syncwarp();
            if (lane == 0) mbar_arrive(EMPTY + slot * 8);

            if (cs == 7) {
                const int s = q >> 3;
                const int nb = s * 192 + (ng * 4) * 8 + t4 * 2;
#pragma unroll
                for (int bt = 0; bt < 4; bt++) {
                    const int c0 = nb + bt * 8;
                    float2 bb = *(const float2*)&b1s[c0];
                    float2 ww = *(const float2*)&w2s[c0];
#pragma unroll
                    for (int mt = 0; mt < 4; mt++) {
                        float* d = C[mt * 4 + bt];
                        accv[mt * 2 + 0] += fmaxf(d[0] + bb.x, 0.f) * ww.x
                                         + fmaxf(d[1] + bb.y, 0.f) * ww.y;
                        accv[mt * 2 + 1] += fmaxf(d[2] + bb.x, 0.f) * ww.x
                                         + fmaxf(d[3] + bb.y, 0.f) * ww.y;
                    }
                }
            }
        }

        // reduce 4 lanes sharing a g-group
#pragma unroll
        for (int i = 0; i < 8; i++) {
            accv[i] += __shfl_xor_sync(0xffffffffu, accv[i], 1);
            accv[i] += __shfl_xor_sync(0xffffffffu, accv[i], 2);
        }

        float* part = (float*)(smem + SM_PART);
        if (t4 == 0) {
#pragma unroll
            for (int mt = 0; mt < 4; mt++) {
                const int row = mg * 64 + mt * 16 + g;
                part[ng * 128 + row]     = accv[mt * 2 + 0];
                part[ng * 128 + row + 8] = accv[mt * 2 + 1];
            }
        }
    }

    __syncthreads();   // consumers wrote part; producer done
    float* part = (float*)(smem + SM_PART);
    if (tid < 128) {
        float v = part[tid] + part[128 + tid] + part[256 + tid]
                + part[384 + tid] + part[512 + tid] + part[640 + tid];
        out[e0 + tid] = v + b2g[0];
    }
}

// ---------------- launch ----------------
extern "C" void kernel_launch(void* const* d_in, const int* in_sizes, int n_in,
                              void* d_out, int out_size) {
    const float* x  = (const float*)d_in[0];
    const int*   ei = (const int*)d_in[1];   // int32 (JAX default: x64 disabled)
    // d_in[2] edge_attr3, d_in[3] edge_attr4, d_in[4] batch: unused by reference
    const float* W1 = (const float*)d_in[5];
    const float* b1 = (const float*)d_in[6];
    const float* W2 = (const float*)d_in[7];
    const float* b2 = (const float*)d_in[8];
    float* out = (float*)d_out;

    prep_w1_kernel<<<(HID * KDIM + 255) / 256, 256>>>(W1);

    cudaFuncSetAttribute(edge_mlp_ws,
                         cudaFuncAttributeMaxDynamicSharedMemorySize, SMEM_TOTAL);
    edge_mlp_ws<<<N_TILES, 416, SMEM_TOTAL>>>(x, ei, b1, W2, b2, out);
}

// round 17
// speedup vs baseline: 1.0781x; 1.0781x over previous
#include <cuda_runtime.h>
#include <cuda_fp16.h>
#include <cstdint>

// Problem constants
#define N_NODES 100000
#define N_EDGES 400000
#define DIM     128
#define KDIM    384       // 3*DIM
#define HID     768       // 6*DIM
#define TILE_M  128
#define N_TILES (N_EDGES / TILE_M)   // 3125
#define KTILES  24
#define N_STEPS 4                    // 768 / 192 n-cols per step
#define CPS     6                    // chunks per step (4 kt each)
#define N_CHUNKS 24                  // 4 steps x 6 chunks

// W1 fp16, m16n8k16 B-fragment order, chunk-grouped:
// [step 4][chunk 6][ntile 24][kt4][lane 32][8B]   (24 KB per chunk)
__device__ __align__(16) __half g_w1frag[HID * KDIM];

static constexpr uint32_t B_STEP_BYTES  = 24 * 24 * 32 * 8;   // 147456
static constexpr uint32_t B_CHUNK_BYTES = B_STEP_BYTES / 6;   // 24576

// ---------------- SMEM layout ----------------
// A (feat frags): [mt8][kt24][lane32][16B] = 98304
static constexpr int SM_A    = 0;
static constexpr int SM_B    = 98304;    // 4 x 24576 ring = 98304
static constexpr int SM_W2   = 196608;   // 768 f32
static constexpr int SM_B1   = 199680;   // 768 f32
static constexpr int SM_PART = 202752;   // 6 x 128 f32 = 3072
static constexpr int SM_MBAR = 205824;   // 4 full + 4 empty mbarriers
static constexpr int SMEM_TOTAL = 205888;

// ---------------- helpers ----------------
__device__ __forceinline__ uint32_t smem_u32(const void* p) {
    uint32_t a;
    asm("{ .reg .u64 t; cvta.to.shared.u64 t, %1; cvt.u32.u64 %0, t; }" : "=r"(a) : "l"(p));
    return a;
}
__device__ __forceinline__ void cp16(uint32_t dst, const void* src) {
    asm volatile("cp.async.cg.shared.global [%0], [%1], 16;" :: "r"(dst), "l"(src) : "memory");
}
__device__ __forceinline__ void cp_arrive_noinc(uint32_t mbar) {
    asm volatile("cp.async.mbarrier.arrive.noinc.shared.b64 [%0];" :: "r"(mbar) : "memory");
}
__device__ __forceinline__ void mbar_init(uint32_t m, uint32_t cnt) {
    asm volatile("mbarrier.init.shared.b64 [%0], %1;" :: "r"(m), "r"(cnt) : "memory");
}
__device__ __forceinline__ void mbar_arrive(uint32_t m) {
    asm volatile("mbarrier.arrive.shared.b64 _, [%0];" :: "r"(m) : "memory");
}
__device__ __forceinline__ void mbar_wait(uint32_t m, uint32_t parity) {
    asm volatile(
        "{\n\t.reg .pred P;\n"
        "LAB%=:\n\t"
        "mbarrier.try_wait.parity.acquire.cta.shared::cta.b64 P, [%0], %1, 0x989680;\n\t"
        "@!P bra LAB%=;\n\t}"
        :: "r"(m), "r"(parity) : "memory");
}
__device__ __forceinline__ void mma16816(float* d, const uint32_t* a, const uint32_t* b) {
    asm volatile(
        "mma.sync.aligned.m16n8k16.row.col.f32.f16.f16.f32 "
        "{%0,%1,%2,%3}, {%4,%5,%6,%7}, {%8,%9}, {%0,%1,%2,%3};"
        : "+f"(d[0]), "+f"(d[1]), "+f"(d[2]), "+f"(d[3])
        : "r"(a[0]), "r"(a[1]), "r"(a[2]), "r"(a[3]), "r"(b[0]), "r"(b[1]));
}

// A-fragment smem byte offset for (row r in 0..127, kpair p in 0..191)
__device__ __forceinline__ uint32_t a_frag_off(int r, int p) {
    int kt   = p >> 3;
    int kp   = p & 7;
    int ln   = ((r & 7) << 2) + (kp & 3);
    int word = ((r >> 3) & 1) + ((kp >> 2) << 1);
    int mt   = r >> 4;
    return (uint32_t)(((mt * KTILES + kt) << 9) + (ln << 4) + (word << 2));
}

// ---------------- prep: W1 fp32 -> fp16 fragment-ordered (4kt-chunk-grouped) ----------------
__global__ void prep_w1_kernel(const float* __restrict__ W1) {
    int i = blockIdx.x * blockDim.x + threadIdx.x;
    if (i >= HID * KDIM) return;
    int n = i / KDIM;
    int k = i - n * KDIM;
    int step = n / 192;           // 192 cols per step
    int np   = n - step * 192;
    int nt   = np >> 3;           // 24 ntiles per step
    int g    = np & 7;
    int kt   = k >> 4;            // 0..23
    int ch   = kt >> 2;           // chunk within step (0..5)
    int kt4  = kt & 3;
    int kk   = k & 15;
    int w    = kk >> 3;
    int t    = (kk & 7) >> 1;
    int hb   = kk & 1;
    uint32_t off = (uint32_t)step * B_STEP_BYTES + (uint32_t)ch * B_CHUNK_BYTES
                 + (uint32_t)((nt * 4 + kt4) << 8)
                 + (uint32_t)(((g << 2) + t) << 3) + (uint32_t)(w << 2) + (uint32_t)(hb << 1);
    *(__half*)((char*)g_w1frag + off) = __float2half_rn(W1[i]);
}

// ---------------- main fused kernel (warp-specialized, 12 consumers + 1 producer) ----------------
__global__ void __launch_bounds__(416, 1) edge_mlp_ws(
    const float* __restrict__ x,
    const int* __restrict__ ei,     // int32 (JAX x64 disabled)
    const float* __restrict__ b1g,
    const float* __restrict__ w2g,
    const float* __restrict__ b2g,
    float* __restrict__ out)
{
    extern __shared__ char smem[];
    const uint32_t sb = smem_u32(smem);
    const int tid  = threadIdx.x;
    const int lane = tid & 31;
    const int wid  = tid >> 5;
    const bool producer = (wid == 12);
    const int e0 = blockIdx.x * TILE_M;

    const uint32_t FULL  = sb + SM_MBAR;       // 4 x 8 B
    const uint32_t EMPTY = sb + SM_MBAR + 32;  // 4 x 8 B

    if (tid == 0) {
#pragma unroll
        for (int i = 0; i < 4; i++) {
            mbar_init(FULL + i * 8, 32);    // producer cp-arrivals (noinc)
            mbar_init(EMPTY + i * 8, 384);  // 12 consumer warps x 32 threads
        }
    }
    __syncthreads();   // barriers initialized

    if (producer) {
        // pre-fill chunks 0..3 (ring initially empty)
#pragma unroll
        for (int q = 0; q < 4; q++) {
            const char* src = (const char*)g_w1frag + (uint32_t)q * B_CHUNK_BYTES + (uint32_t)lane * 16u;
            uint32_t dst = sb + SM_B + (uint32_t)q * B_CHUNK_BYTES + (uint32_t)lane * 16u;
#pragma unroll
            for (int j = 0; j < 48; j++)
                cp16(dst + j * 512, src + j * 512);
            cp_arrive_noinc(FULL + q * 8);
        }
    } else if (tid < 256) {
        // stage w2 / b1
        float* w2s = (float*)(smem + SM_W2);
        float* b1s = (float*)(smem + SM_B1);
#pragma unroll
        for (int i = 0; i < 3; i++) { w2s[tid + i * 256] = w2g[tid + i * 256];
                                      b1s[tid + i * 256] = b1g[tid + i * 256]; }

        // build feat tile (kpair bases: mean 0, prod 64, sqdiff 128); 2 threads/row
        const int r  = tid & 127;
        const int qb = (tid >> 7) * 16;
        const int i0 = ei[e0 + r];
        const int i1 = ei[N_EDGES + e0 + r];
        const float4* p0 = (const float4*)x + (size_t)i0 * 32 + qb;
        const float4* p1 = (const float4*)x + (size_t)i1 * 32 + qb;
        char* As = smem + SM_A;
#pragma unroll 4
        for (int q = 0; q < 16; q++) {
            float4 a = p0[q];
            float4 c = p1[q];
            int qg = qb + q;
            __half2 h;
            h = __floats2half2_rn((a.x + c.x) * 0.5f, (a.y + c.y) * 0.5f);
            *(uint32_t*)(As + a_frag_off(r, 2 * qg))          = *(uint32_t*)&h;
            h = __floats2half2_rn((a.z + c.z) * 0.5f, (a.w + c.w) * 0.5f);
            *(uint32_t*)(As + a_frag_off(r, 2 * qg + 1))      = *(uint32_t*)&h;
            h = __floats2half2_rn(a.x * c.x, a.y * c.y);
            *(uint32_t*)(As + a_frag_off(r, 64 + 2 * qg))     = *(uint32_t*)&h;
            h = __floats2half2_rn(a.z * c.z, a.w * c.w);
            *(uint32_t*)(As + a_frag_off(r, 64 + 2 * qg + 1)) = *(uint32_t*)&h;
            float d0 = a.x - c.x, d1 = a.y - c.y, d2 = a.z - c.z, d3 = a.w - c.w;
            h = __floats2half2_rn(d0 * d0, d1 * d1);
            *(uint32_t*)(As + a_frag_off(r, 128 + 2 * qg))     = *(uint32_t*)&h;
            h = __floats2half2_rn(d2 * d2, d3 * d3);
            *(uint32_t*)(As + a_frag_off(r, 128 + 2 * qg + 1)) = *(uint32_t*)&h;
        }
    }
    __syncthreads();   // A + w2/b1 visible

    if (producer) {
        // steady-state: chunk q into ring slot q&3 after consumers drain q-4
#pragma unroll 1
        for (int q = 4; q < N_CHUNKS; q++) {
            mbar_wait(EMPTY + (q & 3) * 8, ((q >> 2) - 1) & 1);
            const char* src = (const char*)g_w1frag + (uint32_t)q * B_CHUNK_BYTES + (uint32_t)lane * 16u;
            uint32_t dst = sb + SM_B + (uint32_t)(q & 3) * B_CHUNK_BYTES + (uint32_t)lane * 16u;
#pragma unroll
            for (int j = 0; j < 48; j++)
                cp16(dst + j * 512, src + j * 512);
            cp_arrive_noinc(FULL + (q & 3) * 8);
        }
    } else {
        const int mg = wid & 1;      // 2 m-groups (64 rows = 4 mtiles each)
        const int ng = wid >> 1;     // 6 n-groups (32 cols per step each)
        const int t4 = lane & 3;
        const int g  = lane >> 2;
        float* w2s = (float*)(smem + SM_W2);
        float* b1s = (float*)(smem + SM_B1);

        float accv[8];
#pragma unroll
        for (int i = 0; i < 8; i++) accv[i] = 0.f;

        const uint32_t a_base = (uint32_t)SM_A + (uint32_t)(mg * 4 * KTILES) * 512u + (uint32_t)lane * 16u;
        const uint32_t b_rel  = (uint32_t)ng * 4096u + (uint32_t)lane * 8u;   // ntile = ng*4, nt stride 1024

        float C[16][4];
        int cs = 0, s = 0;   // chunk-within-step / step counters (no division)

#pragma unroll 1
        for (int q = 0; q < N_CHUNKS; q++) {
            const int slot = q & 3;
            mbar_wait(FULL + slot * 8, (q >> 2) & 1);

            if (cs == 0) {
#pragma unroll
                for (int f = 0; f < 16; f++)
#pragma unroll
                    for (int v = 0; v < 4; v++) C[f][v] = 0.f;
            }

            const uint32_t bbuf = (uint32_t)SM_B + (uint32_t)slot * B_CHUNK_BYTES + b_rel;
            const int ktb = cs * 4;            // kt base within K for A
            // per-warp kt rotation: breaks LSU/tensor convoys across the 6 ng warps
#pragma unroll
            for (int kk = 0; kk < 4; kk++) {
                const int ktr = (kk + ng) & 3;
                uint4 A0 = *(const uint4*)(smem + a_base + (uint32_t)(0 * KTILES + ktb + ktr) * 512u);
                uint4 A1 = *(const uint4*)(smem + a_base + (uint32_t)(1 * KTILES + ktb + ktr) * 512u);
                uint4 A2 = *(const uint4*)(smem + a_base + (uint32_t)(2 * KTILES + ktb + ktr) * 512u);
                uint4 A3 = *(const uint4*)(smem + a_base + (uint32_t)(3 * KTILES + ktb + ktr) * 512u);
                uint2 B0 = *(const uint2*)(smem + bbuf + (uint32_t)(0 * 1024) + (uint32_t)ktr * 256u);
                uint2 B1 = *(const uint2*)(smem + bbuf + (uint32_t)(1 * 1024) + (uint32_t)ktr * 256u);
                uint2 B2 = *(const uint2*)(smem + bbuf + (uint32_t)(2 * 1024) + (uint32_t)ktr * 256u);
                uint2 B3 = *(const uint2*)(smem + bbuf + (uint32_t)(3 * 1024) + (uint32_t)ktr * 256u);
                mma16816(C[0],  (const uint32_t*)&A0, (const uint32_t*)&B0);
                mma16816(C[1],  (const uint32_t*)&A0, (const uint32_t*)&B1);
                mma16816(C[2],  (const uint32_t*)&A0, (const uint32_t*)&B2);
                mma16816(C[3],  (const uint32_t*)&A0, (const uint32_t*)&B3);
                mma16816(C[4],  (const uint32_t*)&A1, (const uint32_t*)&B0);
                mma16816(C[5],  (const uint32_t*)&A1, (const uint32_t*)&B1);
                mma16816(C[6],  (const uint32_t*)&A1, (const uint32_t*)&B2);
                mma16816(C[7],  (const uint32_t*)&A1, (const uint32_t*)&B3);
                mma16816(C[8],  (const uint32_t*)&A2, (const uint32_t*)&B0);
                mma16816(C[9],  (const uint32_t*)&A2, (const uint32_t*)&B1);
                mma16816(C[10], (const uint32_t*)&A2, (const uint32_t*)&B2);
                mma16816(C[11], (const uint32_t*)&A2, (const uint32_t*)&B3);
                mma16816(C[12], (const uint32_t*)&A3, (const uint32_t*)&B0);
                mma16816(C[13], (const uint32_t*)&A3, (const uint32_t*)&B1);
                mma16816(C[14], (const uint32_t*)&A3, (const uint32_t*)&B2);
                mma16816(C[15], (const uint32_t*)&A3, (const uint32_t*)&B3);
            }
            mbar_arrive(EMPTY + slot * 8);   // slot drained (all 384 threads arrive)

            if (cs == CPS - 1) {
                const int nb = s * 192 + ng * 32 + t4 * 2;
#pragma unroll
                for (int bt = 0; bt < 4; bt++) {
                    const int c0 = nb + bt * 8;
                    float2 bb = *(const float2*)&b1s[c0];
                    float2 ww = *(const float2*)&w2s[c0];
#pragma unroll
                    for (int mt = 0; mt < 4; mt++) {
                        float* d = C[mt * 4 + bt];
                        accv[mt * 2 + 0] += fmaxf(d[0] + bb.x, 0.f) * ww.x
                                         + fmaxf(d[1] + bb.y, 0.f) * ww.y;
                        accv[mt * 2 + 1] += fmaxf(d[2] + bb.x, 0.f) * ww.x
                                         + fmaxf(d[3] + bb.y, 0.f) * ww.y;
                    }
                }
                cs = 0; s++;
            } else {
                cs++;
            }
        }

        // reduce 4 lanes sharing a g-group
#pragma unroll
        for (int i = 0; i < 8; i++) {
            accv[i] += __shfl_xor_sync(0xffffffffu, accv[i], 1);
            accv[i] += __shfl_xor_sync(0xffffffffu, accv[i], 2);
        }

        float* part = (float*)(smem + SM_PART);
        if (t4 == 0) {
#pragma unroll
            for (int mt = 0; mt < 4; mt++) {
                const int row = mg * 64 + mt * 16 + g;
                part[ng * 128 + row]     = accv[mt * 2 + 0];
                part[ng * 128 + row + 8] = accv[mt * 2 + 1];
            }
        }
    }

    __syncthreads();   // consumers wrote part; producer done
    float* part = (float*)(smem + SM_PART);
    if (tid < 128) {
        float v = part[tid] + part[128 + tid] + part[256 + tid]
                + part[384 + tid] + part[512 + tid] + part[640 + tid];
        out[e0 + tid] = v + b2g[0];
    }
}

// ---------------- launch ----------------
extern "C" void kernel_launch(void* const* d_in, const int* in_sizes, int n_in,
                              void* d_out, int out_size) {
    const float* x  = (const float*)d_in[0];
    const int*   ei = (const int*)d_in[1];   // int32 (JAX default: x64 disabled)
    // d_in[2] edge_attr3, d_in[3] edge_attr4, d_in[4] batch: unused by reference
    const float* W1 = (const float*)d_in[5];
    const float* b1 = (const float*)d_in[6];
    const float* W2 = (const float*)d_in[7];
    const float* b2 = (const float*)d_in[8];
    float* out = (float*)d_out;

    prep_w1_kernel<<<(HID * KDIM + 255) / 256, 256>>>(W1);

    cudaFuncSetAttribute(edge_mlp_ws,
                         cudaFuncAttributeMaxDynamicSharedMemorySize, SMEM_TOTAL);
    edge_mlp_ws<<<N_TILES, 416, SMEM_TOTAL>>>(x, ei, b1, W2, b2, out);
}